// round 1
// baseline (speedup 1.0000x reference)
#include <cuda_runtime.h>
#include <cuda_bf16.h>
#include <math_constants.h>

// Shapes (fixed by the problem)
#define B_ 8
#define T_ 1024
#define DIN 512
#define DH 64
#define NH 8
#define BH (B_*NH)          // 64
#define TD (T_*DH)          // 65536 elems per (b,h) slab

#define NEG_INF (-1e30f)

// Scratch for projected K/Q/V, layout [b*8+h][t][d]
__device__ float g_K[BH * TD];
__device__ float g_Q[BH * TD];
__device__ float g_V[BH * TD];

// ---------------------------------------------------------------------------
// Kernel 1: projections  P[b,t,d,h] = sum_i X[b,t,i] * W[i,d,h]
// GEMM view: A = X (M=8192 x K=512), B = W (K=512 x N=512, col n = d*8+h)
// Tile 128x64, BK=16, 256 threads, 8x4 microtile.
// ---------------------------------------------------------------------------
__global__ __launch_bounds__(256) void proj_kernel(
    const float* __restrict__ Xk, const float* __restrict__ Xq, const float* __restrict__ Xv,
    const float* __restrict__ Wk, const float* __restrict__ Wq, const float* __restrict__ Wv)
{
    const float* X; const float* W; float* O;
    int z = blockIdx.z;
    if (z == 0)      { X = Xk; W = Wk; O = g_K; }
    else if (z == 1) { X = Xq; W = Wq; O = g_Q; }
    else             { X = Xv; W = Wv; O = g_V; }

    __shared__ float As[16][128];
    __shared__ float Bs[16][64];

    const int tid = threadIdx.x;
    const int tx = tid & 15;        // 16 col-groups of 4
    const int ty = tid >> 4;        // 16 row-groups of 8
    const int m0 = blockIdx.y * 128;
    const int n0 = blockIdx.x * 64;

    float acc[8][4];
#pragma unroll
    for (int r = 0; r < 8; r++)
#pragma unroll
        for (int c = 0; c < 4; c++) acc[r][c] = 0.f;

    for (int k0 = 0; k0 < DIN; k0 += 16) {
        // A tile: 128 rows x 16 cols = 512 float4, 2 per thread, store transposed
#pragma unroll
        for (int l = 0; l < 2; l++) {
            int f   = tid + l * 256;
            int row = f >> 2;            // 0..127
            int kc  = (f & 3) * 4;       // 0,4,8,12
            float4 v = *(const float4*)(X + (size_t)(m0 + row) * DIN + k0 + kc);
            As[kc + 0][row] = v.x;
            As[kc + 1][row] = v.y;
            As[kc + 2][row] = v.z;
            As[kc + 3][row] = v.w;
        }
        // B tile: 16 x 64 = 256 float4, 1 per thread
        {
            int row = tid >> 4;
            int col = (tid & 15) * 4;
            float4 v = *(const float4*)(W + (size_t)(k0 + row) * 512 + n0 + col);
            *(float4*)&Bs[row][col] = v;
        }
        __syncthreads();

#pragma unroll
        for (int k = 0; k < 16; k++) {
            float a[8], bb[4];
            *(float4*)&a[0] = *(float4*)&As[k][ty * 8];
            *(float4*)&a[4] = *(float4*)&As[k][ty * 8 + 4];
            *(float4*)&bb[0] = *(float4*)&Bs[k][tx * 4];
#pragma unroll
            for (int r = 0; r < 8; r++)
#pragma unroll
                for (int c = 0; c < 4; c++)
                    acc[r][c] += a[r] * bb[c];
        }
        __syncthreads();
    }

    // Epilogue: scatter into [b*8+h][t][d]
#pragma unroll
    for (int r = 0; r < 8; r++) {
        int m = m0 + ty * 8 + r;
        int b = m >> 10;
        int t = m & 1023;
#pragma unroll
        for (int c = 0; c < 4; c++) {
            int n = n0 + tx * 4 + c;
            int d = n >> 3;
            int hh = n & 7;
            O[(size_t)(b * NH + hh) * TD + t * DH + d] = acc[r][c];
        }
    }
}

// ---------------------------------------------------------------------------
// Kernel 2: flash-attention per (b,h). 1 CTA = 128 queries. 64-key tiles.
// scores[i,j] = sum_d Kh[i,d]*Qh[j,d]; mask (causal i>j, pad) -> -inf
// (ref adds -1000 BEFORE /8 => exp(-125) == 0 in fp32, so -inf is exact);
// scale 1/8; online softmax over keys; O[j,d] = sum_i P * V[i,d].
// ---------------------------------------------------------------------------
#define PS_STRIDE 68
#define ATTN_SMEM_FLOATS (64*128 + 64*64 + 64*64 + 128*PS_STRIDE)
#define ATTN_SMEM_BYTES  (ATTN_SMEM_FLOATS*4 + 64*4)

__global__ __launch_bounds__(256, 2) void attn_kernel(
    const int* __restrict__ key_seq, float* __restrict__ out)
{
    extern __shared__ float sm[];
    float* Qs = sm;                   // [64][128]  d-major (transposed)
    float* Ks = Qs + 64 * 128;        // [64][64]   d-major (transposed)
    float* Vs = Ks + 64 * 64;         // [64][64]   k-major
    float* Ps = Vs + 64 * 64;         // [128][PS_STRIDE]
    int*  smask = (int*)(Ps + 128 * PS_STRIDE); // [64]

    const int tid = threadIdx.x;
    const int tx = tid & 15;          // 4 key-cols / 4 d-cols
    const int ty = tid >> 4;          // 8 query-rows
    const int bh = blockIdx.y;
    const int b = bh >> 3, h = bh & 7;
    const int q0 = blockIdx.x * 128;
    const size_t base = (size_t)bh * TD;

    const float* gQp = g_Q + base;
    const float* gKp = g_K + base;
    const float* gVp = g_V + base;

    // Load Q tile transposed: Qs[d][q]
    for (int f = tid; f < 128 * 16; f += 256) {
        int q  = f >> 4;
        int d4 = (f & 15) * 4;
        float4 v = *(const float4*)(gQp + (q0 + q) * DH + d4);
        Qs[(d4 + 0) * 128 + q] = v.x;
        Qs[(d4 + 1) * 128 + q] = v.y;
        Qs[(d4 + 2) * 128 + q] = v.z;
        Qs[(d4 + 3) * 128 + q] = v.w;
    }

    float oacc[8][4];
    float mr[8], lr[8];
#pragma unroll
    for (int r = 0; r < 8; r++) {
        mr[r] = NEG_INF; lr[r] = 0.f;
#pragma unroll
        for (int c = 0; c < 4; c++) oacc[r][c] = 0.f;
    }

    const int kmax = q0 + 128;   // keys beyond this are causally masked for all queries in tile
    for (int kb = 0; kb < kmax; kb += 64) {
        __syncthreads();   // protect Ks/Vs (prev PV) and Ps (prev read)

        // Load K tile transposed + V tile direct
        for (int f = tid; f < 64 * 16; f += 256) {
            int k  = f >> 4;
            int d4 = (f & 15) * 4;
            float4 v = *(const float4*)(gKp + (kb + k) * DH + d4);
            Ks[(d4 + 0) * 64 + k] = v.x;
            Ks[(d4 + 1) * 64 + k] = v.y;
            Ks[(d4 + 2) * 64 + k] = v.z;
            Ks[(d4 + 3) * 64 + k] = v.w;
            float4 w = *(const float4*)(gVp + (kb + k) * DH + d4);
            *(float4*)&Vs[k * 64 + d4] = w;
        }
        if (tid < 64) smask[tid] = key_seq[b * T_ + kb + tid];
        __syncthreads();

        // S = K . Q^T  (per thread: 8 query rows x 4 key cols)
        float s[8][4];
#pragma unroll
        for (int r = 0; r < 8; r++)
#pragma unroll
            for (int c = 0; c < 4; c++) s[r][c] = 0.f;

#pragma unroll 4
        for (int d = 0; d < 64; d++) {
            float a[8], kk[4];
            *(float4*)&a[0] = *(float4*)&Qs[d * 128 + ty * 8];
            *(float4*)&a[4] = *(float4*)&Qs[d * 128 + ty * 8 + 4];
            *(float4*)&kk[0] = *(float4*)&Ks[d * 64 + tx * 4];
#pragma unroll
            for (int r = 0; r < 8; r++)
#pragma unroll
                for (int c = 0; c < 4; c++)
                    s[r][c] += a[r] * kk[c];
        }

        // Mask + scale (mask added pre-scale in ref; exp(-125)==0 in fp32 -> -inf exact)
#pragma unroll
        for (int c = 0; c < 4; c++) {
            int kcol = tx * 4 + c;
            bool pad = (smask[kcol] < 0);
            int ki = kb + kcol;
#pragma unroll
            for (int r = 0; r < 8; r++) {
                int qi = q0 + ty * 8 + r;
                float v = s[r][c] * 0.125f;
                s[r][c] = (pad || (ki > qi)) ? NEG_INF : v;
            }
        }

        // Online softmax stats per query row (reduce over 16-lane tx group)
#pragma unroll
        for (int r = 0; r < 8; r++) {
            float tmax = fmaxf(fmaxf(s[r][0], s[r][1]), fmaxf(s[r][2], s[r][3]));
#pragma unroll
            for (int o = 8; o > 0; o >>= 1)
                tmax = fmaxf(tmax, __shfl_xor_sync(0xffffffffu, tmax, o, 32));
            float mnew  = fmaxf(mr[r], tmax);
            float alpha = __expf(mr[r] - mnew);   // first iter: exp(-inf)=0

            float rsum = 0.f;
#pragma unroll
            for (int c = 0; c < 4; c++) {
                float p = __expf(s[r][c] - mnew); // masked: exp(-1e30) = 0
                s[r][c] = p;
                rsum += p;
            }
#pragma unroll
            for (int o = 8; o > 0; o >>= 1)
                rsum += __shfl_xor_sync(0xffffffffu, rsum, o, 32);

            lr[r] = lr[r] * alpha + rsum;
            mr[r] = mnew;
#pragma unroll
            for (int c = 0; c < 4; c++) oacc[r][c] *= alpha;

            *(float4*)&Ps[(ty * 8 + r) * PS_STRIDE + tx * 4] =
                make_float4(s[r][0], s[r][1], s[r][2], s[r][3]);
        }
        __syncthreads();

        // O += P . V  (per thread: 8 query rows x 4 d cols)
#pragma unroll 2
        for (int i0 = 0; i0 < 64; i0 += 4) {
            float4 vv[4];
#pragma unroll
            for (int ii = 0; ii < 4; ii++)
                vv[ii] = *(float4*)&Vs[(i0 + ii) * 64 + tx * 4];
#pragma unroll
            for (int r = 0; r < 8; r++) {
                float4 pp = *(float4*)&Ps[(ty * 8 + r) * PS_STRIDE + i0];
                float pa[4] = {pp.x, pp.y, pp.z, pp.w};
#pragma unroll
                for (int ii = 0; ii < 4; ii++) {
                    oacc[r][0] += pa[ii] * vv[ii].x;
                    oacc[r][1] += pa[ii] * vv[ii].y;
                    oacc[r][2] += pa[ii] * vv[ii].z;
                    oacc[r][3] += pa[ii] * vv[ii].w;
                }
            }
        }
    }

    // Epilogue: out[b, q, h*64 + d] = O / l
#pragma unroll
    for (int r = 0; r < 8; r++) {
        float inv = 1.f / lr[r];
        int q = q0 + ty * 8 + r;
        float4 o = make_float4(oacc[r][0] * inv, oacc[r][1] * inv,
                               oacc[r][2] * inv, oacc[r][3] * inv);
        *(float4*)(out + (size_t)(b * T_ + q) * (NH * DH) + h * DH + tx * 4) = o;
    }
}

// ---------------------------------------------------------------------------
extern "C" void kernel_launch(void* const* d_in, const int* in_sizes, int n_in,
                              void* d_out, int out_size)
{
    const float* keys    = (const float*)d_in[0];
    const float* queries = (const float*)d_in[1];
    const float* values  = (const float*)d_in[2];
    const float* Wk      = (const float*)d_in[3];
    const float* Wq      = (const float*)d_in[4];
    const float* Wv      = (const float*)d_in[5];
    const int*   key_seq = (const int*)d_in[6];
    float* out = (float*)d_out;

    // Projections: grid (n_tiles=8, m_tiles=64, 3 matrices)
    dim3 g1(512 / 64, (B_ * T_) / 128, 3);
    proj_kernel<<<g1, 256>>>(keys, queries, values, Wk, Wq, Wv);

    // Attention: grid (q_tiles=8, b*h=64)
    cudaFuncSetAttribute(attn_kernel, cudaFuncAttributeMaxDynamicSharedMemorySize,
                         ATTN_SMEM_BYTES);
    dim3 g2(T_ / 128, BH);
    attn_kernel<<<g2, 256, ATTN_SMEM_BYTES>>>(key_seq, out);
}

// round 5
// speedup vs baseline: 1.6626x; 1.6626x over previous
#include <cuda_runtime.h>
#include <cuda_bf16.h>
#include <cstdint>

using std::uint32_t;

// Shapes (fixed by the problem)
#define B_ 8
#define T_ 1024
#define DIN 512
#define DH 64
#define NH 8
#define BH (B_*NH)          // 64
#define TD (T_*DH)          // 65536 elems per (b,h) slab

#define NEG_INF (-1e30f)

// Scratch for projected K/Q/V, layout [b*8+h][t][d]
__device__ float g_K[BH * TD];
__device__ float g_Q[BH * TD];
__device__ float g_V[BH * TD];

__device__ __forceinline__ uint32_t fbits(float x) { return __float_as_uint(x); }

// Split fp32 into tf32-exact hi + residual lo (hi = top 10 mantissa bits).
__device__ __forceinline__ void split_tf32(float x, uint32_t& hi, uint32_t& lo)
{
    uint32_t h = __float_as_uint(x) & 0xFFFFE000u;
    hi = h;
    lo = __float_as_uint(x - __uint_as_float(h));
}

// m16n8k8 tf32 MMA, D += A*B (fp32 accum). Operands are fp32 bits (HW uses tf32).
__device__ __forceinline__ void mma_tf32(float4& d,
    uint32_t a0, uint32_t a1, uint32_t a2, uint32_t a3,
    uint32_t b0, uint32_t b1)
{
    asm volatile(
        "mma.sync.aligned.m16n8k8.row.col.f32.tf32.tf32.f32 "
        "{%0,%1,%2,%3}, {%4,%5,%6,%7}, {%8,%9}, {%0,%1,%2,%3};\n"
        : "+f"(d.x), "+f"(d.y), "+f"(d.z), "+f"(d.w)
        : "r"(a0), "r"(a1), "r"(a2), "r"(a3), "r"(b0), "r"(b1));
}

// ---------------------------------------------------------------------------
// Kernel 1: projection  P[b,t,d,h] = sum_i X[b,t,i] * W[i,d,h]
// GEMM: A = X (8192 x 512), B = W (512 x 512, col n = d*8+h)
// CTA tile 128x64, BK=16, 8 warps (warp tile 32x32), tf32 mma.
// SPLIT=true: 3xTF32 (hi/lo operand split) for near-fp32 accuracy (V path).
// Output selected by WHICH inside device code (NOT via host-passed __device__
// symbol — that was the R4 bug).
// Epilogue staged through smem for coalesced scatter into [bh][t][d].
// ---------------------------------------------------------------------------
#define AS 136   // smem stride for A tile [k][m]  (8k+m -> conflict-free frags)
#define BSS 72   // smem stride for B tile [k][n]

template<bool SPLIT, int WHICH>
__global__ __launch_bounds__(256) void proj_kernel(
    const float* __restrict__ X, const float* __restrict__ W)
{
    float* O = (WHICH == 0) ? g_K : (WHICH == 1) ? g_Q : g_V;

    __shared__ float As_[16 * AS];   // 2176 floats (also reused as epilogue stage)
    __shared__ float Bs_[16 * BSS];

    const int tid  = threadIdx.x;
    const int lane = tid & 31;
    const int w    = tid >> 5;
    const int gid  = lane >> 2;     // 0..7
    const int tig  = lane & 3;      // 0..3
    const int wm   = w & 3;         // 4 M-warps (32 rows each)
    const int wn   = w >> 2;        // 2 N-warps (32 cols each)
    const int m0   = blockIdx.y * 128;
    const int n0   = blockIdx.x * 64;

    float4 acc[2][4];
#pragma unroll
    for (int mt = 0; mt < 2; mt++)
#pragma unroll
        for (int nt = 0; nt < 4; nt++) acc[mt][nt] = make_float4(0.f,0.f,0.f,0.f);

    for (int k0 = 0; k0 < DIN; k0 += 16) {
        __syncthreads();
        // A tile 128x16 -> As_[k][m]
#pragma unroll
        for (int l = 0; l < 2; l++) {
            int f   = tid + l * 256;
            int row = f >> 2;
            int kc  = (f & 3) * 4;
            float4 v = *(const float4*)(X + (size_t)(m0 + row) * DIN + k0 + kc);
            As_[(kc + 0) * AS + row] = v.x;
            As_[(kc + 1) * AS + row] = v.y;
            As_[(kc + 2) * AS + row] = v.z;
            As_[(kc + 3) * AS + row] = v.w;
        }
        // B tile 16x64 -> Bs_[k][n]
        {
            int row = tid >> 4;
            int col = (tid & 15) * 4;
            float4 v = *(const float4*)(W + (size_t)(k0 + row) * 512 + n0 + col);
            *(float4*)&Bs_[row * BSS + col] = v;
        }
        __syncthreads();

#pragma unroll
        for (int ks = 0; ks < 2; ks++) {
            int kb = ks * 8;
            float af[2][4];
#pragma unroll
            for (int mt = 0; mt < 2; mt++) {
                int m = wm * 32 + mt * 16;
                af[mt][0] = As_[(kb + tig)     * AS + m + gid];
                af[mt][1] = As_[(kb + tig)     * AS + m + gid + 8];
                af[mt][2] = As_[(kb + tig + 4) * AS + m + gid];
                af[mt][3] = As_[(kb + tig + 4) * AS + m + gid + 8];
            }
            if (!SPLIT) {
#pragma unroll
                for (int nt = 0; nt < 4; nt++) {
                    int n = wn * 32 + nt * 8;
                    uint32_t b0 = fbits(Bs_[(kb + tig)     * BSS + n + gid]);
                    uint32_t b1 = fbits(Bs_[(kb + tig + 4) * BSS + n + gid]);
#pragma unroll
                    for (int mt = 0; mt < 2; mt++)
                        mma_tf32(acc[mt][nt], fbits(af[mt][0]), fbits(af[mt][1]),
                                 fbits(af[mt][2]), fbits(af[mt][3]), b0, b1);
                }
            } else {
                uint32_t ah[2][4], al[2][4];
#pragma unroll
                for (int mt = 0; mt < 2; mt++)
#pragma unroll
                    for (int r = 0; r < 4; r++)
                        split_tf32(af[mt][r], ah[mt][r], al[mt][r]);
#pragma unroll
                for (int nt = 0; nt < 4; nt++) {
                    int n = wn * 32 + nt * 8;
                    float b0f = Bs_[(kb + tig)     * BSS + n + gid];
                    float b1f = Bs_[(kb + tig + 4) * BSS + n + gid];
                    uint32_t b0h, b0l, b1h, b1l;
                    split_tf32(b0f, b0h, b0l);
                    split_tf32(b1f, b1h, b1l);
#pragma unroll
                    for (int mt = 0; mt < 2; mt++) {
                        mma_tf32(acc[mt][nt], ah[mt][0], ah[mt][1], ah[mt][2], ah[mt][3], b0h, b1h);
                        mma_tf32(acc[mt][nt], al[mt][0], al[mt][1], al[mt][2], al[mt][3], b0h, b1h);
                        mma_tf32(acc[mt][nt], ah[mt][0], ah[mt][1], ah[mt][2], ah[mt][3], b0l, b1l);
                    }
                }
            }
        }
    }

    // Epilogue: stage 32 rows at a time through smem, write coalesced float4.
    float* stage = As_;                 // 32 x 68 = 2176 floats, exact fit
    const int bb = m0 >> 10;            // batch (constant within CTA)
    const int tbase = m0 & 1023;
#pragma unroll 1
    for (int pass = 0; pass < 4; pass++) {
        __syncthreads();
        if (wm == pass) {
#pragma unroll
            for (int mt = 0; mt < 2; mt++) {
#pragma unroll
                for (int nt = 0; nt < 4; nt++) {
                    int rl = mt * 16 + gid;
                    int cl = wn * 32 + nt * 8 + tig * 2;
                    float4 v = acc[mt][nt];
                    *(float2*)&stage[rl * 68 + cl]       = make_float2(v.x, v.y);
                    *(float2*)&stage[(rl + 8) * 68 + cl] = make_float2(v.z, v.w);
                }
            }
        }
        __syncthreads();
        int tpass = tbase + pass * 32;
#pragma unroll
        for (int f = tid; f < 512; f += 256) {
            int dh = f & 1;
            int t  = (f >> 1) & 31;
            int h  = f >> 6;
            int dl0 = dh * 4;
            float4 v;
            v.x = stage[t * 68 + (dl0 + 0) * 8 + h];
            v.y = stage[t * 68 + (dl0 + 1) * 8 + h];
            v.z = stage[t * 68 + (dl0 + 2) * 8 + h];
            v.w = stage[t * 68 + (dl0 + 3) * 8 + h];
            *(float4*)(O + (size_t)(bb * NH + h) * TD + (size_t)(tpass + t) * 64
                         + (n0 >> 3) + dl0) = v;
        }
    }
}

// ---------------------------------------------------------------------------
// Kernel 2: flash attention, tf32 mma. CTA = 128 queries x 1 head, 8 warps,
// warp = 16 query rows. 64-key tiles, online softmax in registers.
// S = QK^T: single tf32 (error damped by softmax; logit std ~0.05).
// PV: 3xTF32 split on both P and V (splits computed in registers; smem
// layout identical to the 1x version, occupancy unchanged).
// ---------------------------------------------------------------------------
#define KSS 68   // Ks stride: bank = 4*gid + tig  -> conflict-free
#define VSS 72   // Vs stride: bank = 8*tig + gid  -> conflict-free
#define PSS 68   // Ps stride (per-warp 16 x 64 tile)

#define ATTN_SMEM_FLOATS (64*KSS + 64*VSS + 8*16*PSS + 64)
#define ATTN_SMEM_BYTES  (ATTN_SMEM_FLOATS * 4)

__global__ __launch_bounds__(256, 2) void attn_kernel(
    const int* __restrict__ key_seq, float* __restrict__ out)
{
    extern __shared__ float sm[];
    float* Ks    = sm;                       // [64][KSS]  (key, d)
    float* Vs    = Ks + 64 * KSS;            // [64][VSS]  (key, d)
    float* Ps    = Vs + 64 * VSS;            // per-warp [16][PSS]
    float* sbias = Ps + 8 * 16 * PSS;        // [64] 0 or -inf per key

    const int tid  = threadIdx.x;
    const int lane = tid & 31;
    const int w    = tid >> 5;
    const int gid  = lane >> 2;
    const int tig  = lane & 3;
    const int bh   = blockIdx.y;
    const int b    = bh >> 3;
    const int q0   = blockIdx.x * 128;
    const size_t base = (size_t)bh * TD;

    const float* gQp = g_Q + base;
    const float* gKp = g_K + base;
    const float* gVp = g_V + base;
    float* Pw = Ps + w * 16 * PSS;

    const int qlo = q0 + w * 16 + gid;
    const int qhi = qlo + 8;

    // Q fragments in registers for the whole loop (A of m16n8k8, row-major)
    uint32_t qa[8][4];
#pragma unroll
    for (int kt = 0; kt < 8; kt++) {
        qa[kt][0] = fbits(gQp[(size_t)qlo * DH + kt * 8 + tig]);
        qa[kt][1] = fbits(gQp[(size_t)qhi * DH + kt * 8 + tig]);
        qa[kt][2] = fbits(gQp[(size_t)qlo * DH + kt * 8 + tig + 4]);
        qa[kt][3] = fbits(gQp[(size_t)qhi * DH + kt * 8 + tig + 4]);
    }

    float4 acc[8];
#pragma unroll
    for (int nt = 0; nt < 8; nt++) acc[nt] = make_float4(0.f,0.f,0.f,0.f);
    float m_lo = NEG_INF, m_hi = NEG_INF, l_lo = 0.f, l_hi = 0.f;

    const int kmax  = q0 + 128;
    const int khi_w = q0 + w * 16 + 16;   // warp skips tiles fully above its rows

    for (int kb = 0; kb < kmax; kb += 64) {
        __syncthreads();
        // Load K/V tiles (coalesced float4), bias per key
        for (int f = tid; f < 64 * 16; f += 256) {
            int k  = f >> 4;
            int d4 = (f & 15) * 4;
            float4 vk = *(const float4*)(gKp + (size_t)(kb + k) * DH + d4);
            *(float4*)&Ks[k * KSS + d4] = vk;
            float4 vv = *(const float4*)(gVp + (size_t)(kb + k) * DH + d4);
            *(float4*)&Vs[k * VSS + d4] = vv;
        }
        if (tid < 64)
            sbias[tid] = (key_seq[b * T_ + kb + tid] < 0) ? NEG_INF : 0.f;
        __syncthreads();

        if (kb >= khi_w) continue;   // fully causally masked for this warp

        // ---- S = Q . K^T  (16 x 64 per warp) ----
        float4 s[8];
#pragma unroll
        for (int nt = 0; nt < 8; nt++) s[nt] = make_float4(0.f,0.f,0.f,0.f);
#pragma unroll
        for (int kt = 0; kt < 8; kt++) {
#pragma unroll
            for (int nt = 0; nt < 8; nt++) {
                uint32_t b0 = fbits(Ks[(nt * 8 + gid) * KSS + kt * 8 + tig]);
                uint32_t b1 = fbits(Ks[(nt * 8 + gid) * KSS + kt * 8 + tig + 4]);
                mma_tf32(s[nt], qa[kt][0], qa[kt][1], qa[kt][2], qa[kt][3], b0, b1);
            }
        }

        // ---- mask + scale (mask pre-scale in ref; underflows to 0 -> -inf ok) ----
        float mx_lo = NEG_INF, mx_hi = NEG_INF;
#pragma unroll
        for (int nt = 0; nt < 8; nt++) {
            int ki  = kb + nt * 8 + tig * 2;
            float b0f = sbias[nt * 8 + tig * 2];
            float b1f = sbias[nt * 8 + tig * 2 + 1];
            s[nt].x = (ki     > qlo) ? NEG_INF : fmaf(s[nt].x, 0.125f, b0f);
            s[nt].y = (ki + 1 > qlo) ? NEG_INF : fmaf(s[nt].y, 0.125f, b1f);
            s[nt].z = (ki     > qhi) ? NEG_INF : fmaf(s[nt].z, 0.125f, b0f);
            s[nt].w = (ki + 1 > qhi) ? NEG_INF : fmaf(s[nt].w, 0.125f, b1f);
            mx_lo = fmaxf(mx_lo, fmaxf(s[nt].x, s[nt].y));
            mx_hi = fmaxf(mx_hi, fmaxf(s[nt].z, s[nt].w));
        }
        mx_lo = fmaxf(mx_lo, __shfl_xor_sync(0xffffffffu, mx_lo, 1));
        mx_lo = fmaxf(mx_lo, __shfl_xor_sync(0xffffffffu, mx_lo, 2));
        mx_hi = fmaxf(mx_hi, __shfl_xor_sync(0xffffffffu, mx_hi, 1));
        mx_hi = fmaxf(mx_hi, __shfl_xor_sync(0xffffffffu, mx_hi, 2));

        float mn_lo = fmaxf(m_lo, mx_lo);
        float mn_hi = fmaxf(m_hi, mx_hi);
        float al_lo = __expf(m_lo - mn_lo);
        float al_hi = __expf(m_hi - mn_hi);

        float sum_lo = 0.f, sum_hi = 0.f;
#pragma unroll
        for (int nt = 0; nt < 8; nt++) {
            s[nt].x = __expf(s[nt].x - mn_lo);
            s[nt].y = __expf(s[nt].y - mn_lo);
            s[nt].z = __expf(s[nt].z - mn_hi);
            s[nt].w = __expf(s[nt].w - mn_hi);
            sum_lo += s[nt].x + s[nt].y;
            sum_hi += s[nt].z + s[nt].w;
        }
        sum_lo += __shfl_xor_sync(0xffffffffu, sum_lo, 1);
        sum_lo += __shfl_xor_sync(0xffffffffu, sum_lo, 2);
        sum_hi += __shfl_xor_sync(0xffffffffu, sum_hi, 1);
        sum_hi += __shfl_xor_sync(0xffffffffu, sum_hi, 2);

        l_lo = l_lo * al_lo + sum_lo;  m_lo = mn_lo;
        l_hi = l_hi * al_hi + sum_hi;  m_hi = mn_hi;

#pragma unroll
        for (int nt = 0; nt < 8; nt++) {
            acc[nt].x *= al_lo;  acc[nt].y *= al_lo;
            acc[nt].z *= al_hi;  acc[nt].w *= al_hi;
        }

        // ---- P -> per-warp smem (D-frag -> A-frag relayout), fp32 ----
#pragma unroll
        for (int nt = 0; nt < 8; nt++) {
            int cl = nt * 8 + tig * 2;
            *(float2*)&Pw[gid * PSS + cl]       = make_float2(s[nt].x, s[nt].y);
            *(float2*)&Pw[(gid + 8) * PSS + cl] = make_float2(s[nt].z, s[nt].w);
        }
        __syncwarp();

        // ---- O += P . V  (3xTF32: split P and V hi/lo in registers) ----
#pragma unroll
        for (int kt = 0; kt < 8; kt++) {
            float a0f = Pw[gid       * PSS + kt * 8 + tig];
            float a1f = Pw[(gid + 8) * PSS + kt * 8 + tig];
            float a2f = Pw[gid       * PSS + kt * 8 + tig + 4];
            float a3f = Pw[(gid + 8) * PSS + kt * 8 + tig + 4];
            uint32_t ah[4], al[4];
            split_tf32(a0f, ah[0], al[0]);
            split_tf32(a1f, ah[1], al[1]);
            split_tf32(a2f, ah[2], al[2]);
            split_tf32(a3f, ah[3], al[3]);
#pragma unroll
            for (int nt = 0; nt < 8; nt++) {
                float b0f = Vs[(kt * 8 + tig)     * VSS + nt * 8 + gid];
                float b1f = Vs[(kt * 8 + tig + 4) * VSS + nt * 8 + gid];
                uint32_t b0h, b0l, b1h, b1l;
                split_tf32(b0f, b0h, b0l);
                split_tf32(b1f, b1h, b1l);
                mma_tf32(acc[nt], ah[0], ah[1], ah[2], ah[3], b0h, b1h);
                mma_tf32(acc[nt], al[0], al[1], al[2], al[3], b0h, b1h);
                mma_tf32(acc[nt], ah[0], ah[1], ah[2], ah[3], b0l, b1l);
            }
        }
    }

    // Epilogue: out[b, q, h*64 + d] = O / l
    const int h = bh & 7;
    float il_lo = 1.f / l_lo;
    float il_hi = 1.f / l_hi;
#pragma unroll
    for (int nt = 0; nt < 8; nt++) {
        int col = h * DH + nt * 8 + tig * 2;
        *(float2*)(out + (size_t)(b * T_ + qlo) * (NH * DH) + col) =
            make_float2(acc[nt].x * il_lo, acc[nt].y * il_lo);
        *(float2*)(out + (size_t)(b * T_ + qhi) * (NH * DH) + col) =
            make_float2(acc[nt].z * il_hi, acc[nt].w * il_hi);
    }
}

// ---------------------------------------------------------------------------
extern "C" void kernel_launch(void* const* d_in, const int* in_sizes, int n_in,
                              void* d_out, int out_size)
{
    const float* keys    = (const float*)d_in[0];
    const float* queries = (const float*)d_in[1];
    const float* values  = (const float*)d_in[2];
    const float* Wk      = (const float*)d_in[3];
    const float* Wq      = (const float*)d_in[4];
    const float* Wv      = (const float*)d_in[5];
    const int*   key_seq = (const int*)d_in[6];
    float* out = (float*)d_out;

    dim3 g1(512 / 64, (B_ * T_) / 128);
    proj_kernel<false, 0><<<g1, 256>>>(keys,    Wk);
    proj_kernel<false, 1><<<g1, 256>>>(queries, Wq);
    proj_kernel<true,  2><<<g1, 256>>>(values,  Wv);

    cudaFuncSetAttribute(attn_kernel, cudaFuncAttributeMaxDynamicSharedMemorySize,
                         ATTN_SMEM_BYTES);
    dim3 g2(T_ / 128, BH);
    attn_kernel<<<g2, 256, ATTN_SMEM_BYTES>>>(key_seq, out);
}

// round 6
// speedup vs baseline: 1.7463x; 1.0504x over previous
#include <cuda_runtime.h>
#include <cuda_bf16.h>
#include <cstdint>

using std::uint32_t;

// Shapes (fixed by the problem)
#define B_ 8
#define T_ 1024
#define DIN 512
#define DH 64
#define NH 8
#define BH (B_*NH)          // 64
#define TD (T_*DH)          // 65536 elems per (b,h) slab

#define NEG_INF (-1e30f)

// Scratch: projected K/Q, and V split into tf32-hi / residual-lo parts.
// Layout [b*8+h][t][d].
__device__ float g_K [BH * TD];
__device__ float g_Q [BH * TD];
__device__ float g_Vh[BH * TD];
__device__ float g_Vl[BH * TD];

__device__ __forceinline__ uint32_t fbits(float x) { return __float_as_uint(x); }
__device__ __forceinline__ float tf32_hi(float x)
{ return __uint_as_float(__float_as_uint(x) & 0xFFFFE000u); }

// Split fp32 into tf32-exact hi + residual lo.
__device__ __forceinline__ void split_tf32(float x, uint32_t& hi, uint32_t& lo)
{
    float h = tf32_hi(x);
    hi = __float_as_uint(h);
    lo = __float_as_uint(x - h);
}

// m16n8k8 tf32 MMA, D += A*B (fp32 accum).
__device__ __forceinline__ void mma_tf32(float4& d,
    uint32_t a0, uint32_t a1, uint32_t a2, uint32_t a3,
    uint32_t b0, uint32_t b1)
{
    asm volatile(
        "mma.sync.aligned.m16n8k8.row.col.f32.tf32.tf32.f32 "
        "{%0,%1,%2,%3}, {%4,%5,%6,%7}, {%8,%9}, {%0,%1,%2,%3};\n"
        : "+f"(d.x), "+f"(d.y), "+f"(d.z), "+f"(d.w)
        : "r"(a0), "r"(a1), "r"(a2), "r"(a3), "r"(b0), "r"(b1));
}

// ---------------------------------------------------------------------------
// Kernel 1: projection  P[b,t,d,h] = sum_i X[b,t,i] * W[i,d,h]
// CTA tile 128x64, BK=16, 8 warps (warp tile 32x32), tf32 mma.
// LDG-prefetch software pipeline: tile s+1 loaded into registers while
// computing tile s.
// SPLIT=true (V path): 3xTF32 accumulate; epilogue writes hi/lo arrays.
// ---------------------------------------------------------------------------
#define AS 136   // smem stride for A tile [k][m]
#define BSS 72   // smem stride for B tile [k][n]

template<bool SPLIT, int WHICH>
__global__ __launch_bounds__(256) void proj_kernel(
    const float* __restrict__ X, const float* __restrict__ W)
{
    __shared__ float As_[16 * AS];   // also reused as epilogue stage
    __shared__ float Bs_[16 * BSS];

    const int tid  = threadIdx.x;
    const int lane = tid & 31;
    const int w    = tid >> 5;
    const int gid  = lane >> 2;     // 0..7
    const int tig  = lane & 3;      // 0..3
    const int wm   = w & 3;         // 4 M-warps (32 rows each)
    const int wn   = w >> 2;        // 2 N-warps (32 cols each)
    const int m0   = blockIdx.y * 128;
    const int n0   = blockIdx.x * 64;

    // prefetch addressing (fixed per thread)
    const int arow0 = tid >> 2;            // A: rows tid/4 and +64
    const int akc   = (tid & 3) * 4;
    const int brow  = tid >> 4;
    const int bcol  = (tid & 15) * 4;

    float4 pa0, pa1, pb;

    auto ldg_tile = [&](int k0) {
        pa0 = *(const float4*)(X + (size_t)(m0 + arow0)      * DIN + k0 + akc);
        pa1 = *(const float4*)(X + (size_t)(m0 + arow0 + 64) * DIN + k0 + akc);
        pb  = *(const float4*)(W + (size_t)(k0 + brow) * 512 + n0 + bcol);
    };
    auto sts_tile = [&]() {
        As_[(akc + 0) * AS + arow0] = pa0.x;
        As_[(akc + 1) * AS + arow0] = pa0.y;
        As_[(akc + 2) * AS + arow0] = pa0.z;
        As_[(akc + 3) * AS + arow0] = pa0.w;
        As_[(akc + 0) * AS + arow0 + 64] = pa1.x;
        As_[(akc + 1) * AS + arow0 + 64] = pa1.y;
        As_[(akc + 2) * AS + arow0 + 64] = pa1.z;
        As_[(akc + 3) * AS + arow0 + 64] = pa1.w;
        *(float4*)&Bs_[brow * BSS + bcol] = pb;
    };

    float4 acc[2][4];
#pragma unroll
    for (int mt = 0; mt < 2; mt++)
#pragma unroll
        for (int nt = 0; nt < 4; nt++) acc[mt][nt] = make_float4(0.f,0.f,0.f,0.f);

    // prologue
    ldg_tile(0);
    sts_tile();
    __syncthreads();

#pragma unroll 1
    for (int s = 0; s < 32; s++) {
        const bool has_next = (s + 1 < 32);
        if (has_next) ldg_tile((s + 1) * 16);

        // compute tile s from smem
#pragma unroll
        for (int ks = 0; ks < 2; ks++) {
            int kb = ks * 8;
            float af[2][4];
#pragma unroll
            for (int mt = 0; mt < 2; mt++) {
                int m = wm * 32 + mt * 16;
                af[mt][0] = As_[(kb + tig)     * AS + m + gid];
                af[mt][1] = As_[(kb + tig)     * AS + m + gid + 8];
                af[mt][2] = As_[(kb + tig + 4) * AS + m + gid];
                af[mt][3] = As_[(kb + tig + 4) * AS + m + gid + 8];
            }
            if (!SPLIT) {
#pragma unroll
                for (int nt = 0; nt < 4; nt++) {
                    int n = wn * 32 + nt * 8;
                    uint32_t b0 = fbits(Bs_[(kb + tig)     * BSS + n + gid]);
                    uint32_t b1 = fbits(Bs_[(kb + tig + 4) * BSS + n + gid]);
#pragma unroll
                    for (int mt = 0; mt < 2; mt++)
                        mma_tf32(acc[mt][nt], fbits(af[mt][0]), fbits(af[mt][1]),
                                 fbits(af[mt][2]), fbits(af[mt][3]), b0, b1);
                }
            } else {
                uint32_t ah[2][4], al[2][4];
#pragma unroll
                for (int mt = 0; mt < 2; mt++)
#pragma unroll
                    for (int r = 0; r < 4; r++)
                        split_tf32(af[mt][r], ah[mt][r], al[mt][r]);
#pragma unroll
                for (int nt = 0; nt < 4; nt++) {
                    int n = wn * 32 + nt * 8;
                    uint32_t b0h, b0l, b1h, b1l;
                    split_tf32(Bs_[(kb + tig)     * BSS + n + gid], b0h, b0l);
                    split_tf32(Bs_[(kb + tig + 4) * BSS + n + gid], b1h, b1l);
#pragma unroll
                    for (int mt = 0; mt < 2; mt++) {
                        mma_tf32(acc[mt][nt], ah[mt][0], ah[mt][1], ah[mt][2], ah[mt][3], b0h, b1h);
                        mma_tf32(acc[mt][nt], al[mt][0], al[mt][1], al[mt][2], al[mt][3], b0h, b1h);
                        mma_tf32(acc[mt][nt], ah[mt][0], ah[mt][1], ah[mt][2], ah[mt][3], b0l, b1l);
                    }
                }
            }
        }

        __syncthreads();
        if (has_next) {
            sts_tile();
            __syncthreads();
        }
    }

    // Epilogue: stage 32 rows at a time through smem, write coalesced float4.
    float* stage = As_;                 // 32 x 68 = 2176 floats, exact fit
    const int bb = m0 >> 10;
    const int tbase = m0 & 1023;
#pragma unroll 1
    for (int pass = 0; pass < 4; pass++) {
        __syncthreads();
        if (wm == pass) {
#pragma unroll
            for (int mt = 0; mt < 2; mt++) {
#pragma unroll
                for (int nt = 0; nt < 4; nt++) {
                    int rl = mt * 16 + gid;
                    int cl = wn * 32 + nt * 8 + tig * 2;
                    float4 v = acc[mt][nt];
                    *(float2*)&stage[rl * 68 + cl]       = make_float2(v.x, v.y);
                    *(float2*)&stage[(rl + 8) * 68 + cl] = make_float2(v.z, v.w);
                }
            }
        }
        __syncthreads();
        int tpass = tbase + pass * 32;
#pragma unroll
        for (int f = tid; f < 512; f += 256) {
            int dh = f & 1;
            int t  = (f >> 1) & 31;
            int h  = f >> 6;
            int dl0 = dh * 4;
            float4 v;
            v.x = stage[t * 68 + (dl0 + 0) * 8 + h];
            v.y = stage[t * 68 + (dl0 + 1) * 8 + h];
            v.z = stage[t * 68 + (dl0 + 2) * 8 + h];
            v.w = stage[t * 68 + (dl0 + 3) * 8 + h];
            size_t off = (size_t)(bb * NH + h) * TD + (size_t)(tpass + t) * 64
                         + (n0 >> 3) + dl0;
            if (WHICH == 0) {
                *(float4*)(g_K + off) = v;
            } else if (WHICH == 1) {
                *(float4*)(g_Q + off) = v;
            } else {
                float4 hi, lo;
                hi.x = tf32_hi(v.x); lo.x = v.x - hi.x;
                hi.y = tf32_hi(v.y); lo.y = v.y - hi.y;
                hi.z = tf32_hi(v.z); lo.z = v.z - hi.z;
                hi.w = tf32_hi(v.w); lo.w = v.w - hi.w;
                *(float4*)(g_Vh + off) = hi;
                *(float4*)(g_Vl + off) = lo;
            }
        }
    }
}

// ---------------------------------------------------------------------------
// Kernel 2: flash attention, tf32 mma. Each CTA processes TWO q-blocks of
// 128 rows, paired (j, 7-j) so every CTA does exactly 18 key-tiles total
// -> 256 uniform CTAs = single wave at occupancy 2.
// S = QK^T: 1x tf32. PV: 3xTF32 with P split in registers and V hi/lo
// precomputed by the projection kernel (bit-identical to in-kernel split).
// ---------------------------------------------------------------------------
#define KSS 68   // Ks stride: conflict-free frag gathers
#define VSS 72   // Vhs/Vls stride
#define PSS 68   // per-warp P tile stride

#define ATTN_SMEM_FLOATS (64*KSS + 64*VSS + 64*VSS + 8*16*PSS + 64)
#define ATTN_SMEM_BYTES  (ATTN_SMEM_FLOATS * 4)

__global__ __launch_bounds__(256, 2) void attn_kernel(
    const int* __restrict__ key_seq, float* __restrict__ out)
{
    extern __shared__ float sm[];
    float* Ks    = sm;                        // [64][KSS]
    float* Vhs   = Ks  + 64 * KSS;            // [64][VSS]
    float* Vls   = Vhs + 64 * VSS;            // [64][VSS]
    float* Ps    = Vls + 64 * VSS;            // per-warp [16][PSS]
    float* sbias = Ps + 8 * 16 * PSS;         // [64]

    const int tid  = threadIdx.x;
    const int lane = tid & 31;
    const int w    = tid >> 5;
    const int gid  = lane >> 2;
    const int tig  = lane & 3;
    const int bh   = blockIdx.y;
    const int b    = bh >> 3;
    const int h    = bh & 7;
    const size_t base = (size_t)bh * TD;

    const float* gQp  = g_Q  + base;
    const float* gKp  = g_K  + base;
    const float* gVhp = g_Vh + base;
    const float* gVlp = g_Vl + base;
    const int*   ksq  = key_seq + b * T_;
    float* Pw = Ps + w * 16 * PSS;

#pragma unroll 1
    for (int pi = 0; pi < 2; pi++) {
        const int blk = pi ? (7 - blockIdx.x) : blockIdx.x;
        const int q0  = blk * 128;
        const int qlo = q0 + w * 16 + gid;
        const int qhi = qlo + 8;

        // Q fragments in registers for this block
        uint32_t qa[8][4];
#pragma unroll
        for (int kt = 0; kt < 8; kt++) {
            qa[kt][0] = fbits(gQp[(size_t)qlo * DH + kt * 8 + tig]);
            qa[kt][1] = fbits(gQp[(size_t)qhi * DH + kt * 8 + tig]);
            qa[kt][2] = fbits(gQp[(size_t)qlo * DH + kt * 8 + tig + 4]);
            qa[kt][3] = fbits(gQp[(size_t)qhi * DH + kt * 8 + tig + 4]);
        }

        float4 acc[8];
#pragma unroll
        for (int nt = 0; nt < 8; nt++) acc[nt] = make_float4(0.f,0.f,0.f,0.f);
        float m_lo = NEG_INF, m_hi = NEG_INF, l_lo = 0.f, l_hi = 0.f;

        const int kmax  = q0 + 128;
        const int khi_w = q0 + w * 16 + 16;

        for (int kb = 0; kb < kmax; kb += 64) {
            __syncthreads();   // protect Ks/Vhs/Vls vs previous tile readers
            for (int f = tid; f < 64 * 16; f += 256) {
                int k  = f >> 4;
                int d4 = (f & 15) * 4;
                size_t goff = (size_t)(kb + k) * DH + d4;
                *(float4*)&Ks [k * KSS + d4] = *(const float4*)(gKp  + goff);
                *(float4*)&Vhs[k * VSS + d4] = *(const float4*)(gVhp + goff);
                *(float4*)&Vls[k * VSS + d4] = *(const float4*)(gVlp + goff);
            }
            if (tid < 64)
                sbias[tid] = (ksq[kb + tid] < 0) ? NEG_INF : 0.f;
            __syncthreads();

            if (kb >= khi_w) continue;   // fully causally masked for this warp

            // ---- S = Q . K^T ----
            float4 s[8];
#pragma unroll
            for (int nt = 0; nt < 8; nt++) s[nt] = make_float4(0.f,0.f,0.f,0.f);
#pragma unroll
            for (int kt = 0; kt < 8; kt++) {
#pragma unroll
                for (int nt = 0; nt < 8; nt++) {
                    uint32_t b0 = fbits(Ks[(nt * 8 + gid) * KSS + kt * 8 + tig]);
                    uint32_t b1 = fbits(Ks[(nt * 8 + gid) * KSS + kt * 8 + tig + 4]);
                    mma_tf32(s[nt], qa[kt][0], qa[kt][1], qa[kt][2], qa[kt][3], b0, b1);
                }
            }

            // ---- mask + scale ----
            float mx_lo = NEG_INF, mx_hi = NEG_INF;
#pragma unroll
            for (int nt = 0; nt < 8; nt++) {
                int ki  = kb + nt * 8 + tig * 2;
                float b0f = sbias[nt * 8 + tig * 2];
                float b1f = sbias[nt * 8 + tig * 2 + 1];
                s[nt].x = (ki     > qlo) ? NEG_INF : fmaf(s[nt].x, 0.125f, b0f);
                s[nt].y = (ki + 1 > qlo) ? NEG_INF : fmaf(s[nt].y, 0.125f, b1f);
                s[nt].z = (ki     > qhi) ? NEG_INF : fmaf(s[nt].z, 0.125f, b0f);
                s[nt].w = (ki + 1 > qhi) ? NEG_INF : fmaf(s[nt].w, 0.125f, b1f);
                mx_lo = fmaxf(mx_lo, fmaxf(s[nt].x, s[nt].y));
                mx_hi = fmaxf(mx_hi, fmaxf(s[nt].z, s[nt].w));
            }
            mx_lo = fmaxf(mx_lo, __shfl_xor_sync(0xffffffffu, mx_lo, 1));
            mx_lo = fmaxf(mx_lo, __shfl_xor_sync(0xffffffffu, mx_lo, 2));
            mx_hi = fmaxf(mx_hi, __shfl_xor_sync(0xffffffffu, mx_hi, 1));
            mx_hi = fmaxf(mx_hi, __shfl_xor_sync(0xffffffffu, mx_hi, 2));

            float mn_lo = fmaxf(m_lo, mx_lo);
            float mn_hi = fmaxf(m_hi, mx_hi);
            float al_lo = __expf(m_lo - mn_lo);
            float al_hi = __expf(m_hi - mn_hi);

            float sum_lo = 0.f, sum_hi = 0.f;
#pragma unroll
            for (int nt = 0; nt < 8; nt++) {
                s[nt].x = __expf(s[nt].x - mn_lo);
                s[nt].y = __expf(s[nt].y - mn_lo);
                s[nt].z = __expf(s[nt].z - mn_hi);
                s[nt].w = __expf(s[nt].w - mn_hi);
                sum_lo += s[nt].x + s[nt].y;
                sum_hi += s[nt].z + s[nt].w;
            }
            sum_lo += __shfl_xor_sync(0xffffffffu, sum_lo, 1);
            sum_lo += __shfl_xor_sync(0xffffffffu, sum_lo, 2);
            sum_hi += __shfl_xor_sync(0xffffffffu, sum_hi, 1);
            sum_hi += __shfl_xor_sync(0xffffffffu, sum_hi, 2);

            l_lo = l_lo * al_lo + sum_lo;  m_lo = mn_lo;
            l_hi = l_hi * al_hi + sum_hi;  m_hi = mn_hi;

#pragma unroll
            for (int nt = 0; nt < 8; nt++) {
                acc[nt].x *= al_lo;  acc[nt].y *= al_lo;
                acc[nt].z *= al_hi;  acc[nt].w *= al_hi;
            }

            // ---- P -> per-warp smem (D-frag -> A-frag relayout) ----
#pragma unroll
            for (int nt = 0; nt < 8; nt++) {
                int cl = nt * 8 + tig * 2;
                *(float2*)&Pw[gid * PSS + cl]       = make_float2(s[nt].x, s[nt].y);
                *(float2*)&Pw[(gid + 8) * PSS + cl] = make_float2(s[nt].z, s[nt].w);
            }
            __syncwarp();

            // ---- O += P . V  (3xTF32: P split in regs, V hi/lo from smem) ----
#pragma unroll
            for (int kt = 0; kt < 8; kt++) {
                uint32_t ah[4], al[4];
                split_tf32(Pw[gid       * PSS + kt * 8 + tig],     ah[0], al[0]);
                split_tf32(Pw[(gid + 8) * PSS + kt * 8 + tig],     ah[1], al[1]);
                split_tf32(Pw[gid       * PSS + kt * 8 + tig + 4], ah[2], al[2]);
                split_tf32(Pw[(gid + 8) * PSS + kt * 8 + tig + 4], ah[3], al[3]);
#pragma unroll
                for (int nt = 0; nt < 8; nt++) {
                    int r0 = (kt * 8 + tig) * VSS + nt * 8 + gid;
                    int r1 = (kt * 8 + tig + 4) * VSS + nt * 8 + gid;
                    uint32_t b0h = fbits(Vhs[r0]);
                    uint32_t b1h = fbits(Vhs[r1]);
                    uint32_t b0l = fbits(Vls[r0]);
                    uint32_t b1l = fbits(Vls[r1]);
                    mma_tf32(acc[nt], ah[0], ah[1], ah[2], ah[3], b0h, b1h);
                    mma_tf32(acc[nt], al[0], al[1], al[2], al[3], b0h, b1h);
                    mma_tf32(acc[nt], ah[0], ah[1], ah[2], ah[3], b0l, b1l);
                }
            }
        }

        // Epilogue for this q-block
        float il_lo = 1.f / l_lo;
        float il_hi = 1.f / l_hi;
#pragma unroll
        for (int nt = 0; nt < 8; nt++) {
            int col = h * DH + nt * 8 + tig * 2;
            *(float2*)(out + (size_t)(b * T_ + qlo) * (NH * DH) + col) =
                make_float2(acc[nt].x * il_lo, acc[nt].y * il_lo);
            *(float2*)(out + (size_t)(b * T_ + qhi) * (NH * DH) + col) =
                make_float2(acc[nt].z * il_hi, acc[nt].w * il_hi);
        }
    }
}

// ---------------------------------------------------------------------------
extern "C" void kernel_launch(void* const* d_in, const int* in_sizes, int n_in,
                              void* d_out, int out_size)
{
    const float* keys    = (const float*)d_in[0];
    const float* queries = (const float*)d_in[1];
    const float* values  = (const float*)d_in[2];
    const float* Wk      = (const float*)d_in[3];
    const float* Wq      = (const float*)d_in[4];
    const float* Wv      = (const float*)d_in[5];
    const int*   key_seq = (const int*)d_in[6];
    float* out = (float*)d_out;

    dim3 g1(512 / 64, (B_ * T_) / 128);
    proj_kernel<false, 0><<<g1, 256>>>(keys,    Wk);
    proj_kernel<false, 1><<<g1, 256>>>(queries, Wq);
    proj_kernel<true,  2><<<g1, 256>>>(values,  Wv);

    cudaFuncSetAttribute(attn_kernel, cudaFuncAttributeMaxDynamicSharedMemorySize,
                         ATTN_SMEM_BYTES);
    dim3 g2(4, BH);   // 4 paired q-block CTAs x 64 (b,h) = 256 uniform CTAs
    attn_kernel<<<g2, 256, ATTN_SMEM_BYTES>>>(key_seq, out);
}

// round 8
// speedup vs baseline: 1.8968x; 1.0862x over previous
#include <cuda_runtime.h>
#include <cuda_bf16.h>
#include <cstdint>

using std::uint32_t;

// Shapes (fixed by the problem)
#define B_ 8
#define T_ 1024
#define DIN 512
#define DH 64
#define NH 8
#define BH (B_*NH)          // 64
#define TD (T_*DH)          // 65536 elems per (b,h) slab

#define NEG_INF (-1e30f)

// Scratch (bf16 hi/lo splits of the fp32-accurate projections):
//  K,Q: [bh][t][d] row-major.  V: TRANSPOSED [bh][d][t] (k-pairs along t).
__device__ __nv_bfloat16 g_Kh [BH * TD];
__device__ __nv_bfloat16 g_Kl [BH * TD];
__device__ __nv_bfloat16 g_Qh [BH * TD];
__device__ __nv_bfloat16 g_Ql [BH * TD];
__device__ __nv_bfloat16 g_Vth[BH * TD];
__device__ __nv_bfloat16 g_Vtl[BH * TD];

__device__ __forceinline__ uint32_t fbits(float x) { return __float_as_uint(x); }
__device__ __forceinline__ float tf32_hi(float x)
{ return __uint_as_float(__float_as_uint(x) & 0xFFFFE000u); }

__device__ __forceinline__ void split_tf32(float x, uint32_t& hi, uint32_t& lo)
{
    float h = tf32_hi(x);
    hi = __float_as_uint(h);
    lo = __float_as_uint(x - h);
}

// bf16 hi/lo split: hi = rn(x), lo = rn(x - hi). hi+lo ~ 16 mantissa bits.
__device__ __forceinline__ void bf_split(float x, __nv_bfloat16& h, __nv_bfloat16& l)
{
    h = __float2bfloat16(x);
    l = __float2bfloat16(x - __bfloat162float(h));
}
__device__ __forceinline__ uint32_t pack_bf2(__nv_bfloat16 a, __nv_bfloat16 b)
{
    __nv_bfloat162 t; t.x = a; t.y = b;
    return *reinterpret_cast<uint32_t*>(&t);
}

// legacy m16n8k8 tf32 MMA (projection kernel)
__device__ __forceinline__ void mma_tf32(float4& d,
    uint32_t a0, uint32_t a1, uint32_t a2, uint32_t a3,
    uint32_t b0, uint32_t b1)
{
    asm volatile(
        "mma.sync.aligned.m16n8k8.row.col.f32.tf32.tf32.f32 "
        "{%0,%1,%2,%3}, {%4,%5,%6,%7}, {%8,%9}, {%0,%1,%2,%3};\n"
        : "+f"(d.x), "+f"(d.y), "+f"(d.z), "+f"(d.w)
        : "r"(a0), "r"(a1), "r"(a2), "r"(a3), "r"(b0), "r"(b1));
}

// legacy m16n8k16 bf16 MMA (attention kernel), fp32 accum
__device__ __forceinline__ void mma_bf16(float4& d,
    uint32_t a0, uint32_t a1, uint32_t a2, uint32_t a3,
    uint32_t b0, uint32_t b1)
{
    asm volatile(
        "mma.sync.aligned.m16n8k16.row.col.f32.bf16.bf16.f32 "
        "{%0,%1,%2,%3}, {%4,%5,%6,%7}, {%8,%9}, {%0,%1,%2,%3};\n"
        : "+f"(d.x), "+f"(d.y), "+f"(d.z), "+f"(d.w)
        : "r"(a0), "r"(a1), "r"(a2), "r"(a3), "r"(b0), "r"(b1));
}

// ---------------------------------------------------------------------------
// Kernel 1: projection (tf32 mma, unchanged math from R6 — verified).
// SPLIT=true (V): 3xTF32. Epilogue emits bf16 hi/lo; V transposed [d][t].
// ---------------------------------------------------------------------------
#define AS 136
#define BSS 72

template<bool SPLIT, int WHICH>
__global__ __launch_bounds__(256) void proj_kernel(
    const float* __restrict__ X, const float* __restrict__ W)
{
    __shared__ float As_[16 * AS];   // reused as epilogue stage (32x68=2176)
    __shared__ float Bs_[16 * BSS];

    const int tid  = threadIdx.x;
    const int lane = tid & 31;
    const int w    = tid >> 5;
    const int gid  = lane >> 2;
    const int tig  = lane & 3;
    const int wm   = w & 3;
    const int wn   = w >> 2;
    const int m0   = blockIdx.y * 128;
    const int n0   = blockIdx.x * 64;

    // prefetch addressing
    const int arow0 = tid >> 2;
    const int akc   = (tid & 3) * 4;
    const int brow  = tid >> 4;
    const int bcol  = (tid & 15) * 4;

    float4 pa0, pa1, pb;
    auto ldg_tile = [&](int k0) {
        pa0 = *(const float4*)(X + (size_t)(m0 + arow0)      * DIN + k0 + akc);
        pa1 = *(const float4*)(X + (size_t)(m0 + arow0 + 64) * DIN + k0 + akc);
        pb  = *(const float4*)(W + (size_t)(k0 + brow) * 512 + n0 + bcol);
    };
    auto sts_tile = [&]() {
        As_[(akc + 0) * AS + arow0] = pa0.x;
        As_[(akc + 1) * AS + arow0] = pa0.y;
        As_[(akc + 2) * AS + arow0] = pa0.z;
        As_[(akc + 3) * AS + arow0] = pa0.w;
        As_[(akc + 0) * AS + arow0 + 64] = pa1.x;
        As_[(akc + 1) * AS + arow0 + 64] = pa1.y;
        As_[(akc + 2) * AS + arow0 + 64] = pa1.z;
        As_[(akc + 3) * AS + arow0 + 64] = pa1.w;
        *(float4*)&Bs_[brow * BSS + bcol] = pb;
    };

    float4 acc[2][4];
#pragma unroll
    for (int mt = 0; mt < 2; mt++)
#pragma unroll
        for (int nt = 0; nt < 4; nt++) acc[mt][nt] = make_float4(0.f,0.f,0.f,0.f);

    ldg_tile(0);
    sts_tile();
    __syncthreads();

#pragma unroll 1
    for (int s = 0; s < 32; s++) {
        const bool has_next = (s + 1 < 32);
        if (has_next) ldg_tile((s + 1) * 16);

#pragma unroll
        for (int ks = 0; ks < 2; ks++) {
            int kb = ks * 8;
            float af[2][4];
#pragma unroll
            for (int mt = 0; mt < 2; mt++) {
                int m = wm * 32 + mt * 16;
                af[mt][0] = As_[(kb + tig)     * AS + m + gid];
                af[mt][1] = As_[(kb + tig)     * AS + m + gid + 8];
                af[mt][2] = As_[(kb + tig + 4) * AS + m + gid];
                af[mt][3] = As_[(kb + tig + 4) * AS + m + gid + 8];
            }
            if (!SPLIT) {
#pragma unroll
                for (int nt = 0; nt < 4; nt++) {
                    int n = wn * 32 + nt * 8;
                    uint32_t b0 = fbits(Bs_[(kb + tig)     * BSS + n + gid]);
                    uint32_t b1 = fbits(Bs_[(kb + tig + 4) * BSS + n + gid]);
#pragma unroll
                    for (int mt = 0; mt < 2; mt++)
                        mma_tf32(acc[mt][nt], fbits(af[mt][0]), fbits(af[mt][1]),
                                 fbits(af[mt][2]), fbits(af[mt][3]), b0, b1);
                }
            } else {
                uint32_t ah[2][4], al[2][4];
#pragma unroll
                for (int mt = 0; mt < 2; mt++)
#pragma unroll
                    for (int r = 0; r < 4; r++)
                        split_tf32(af[mt][r], ah[mt][r], al[mt][r]);
#pragma unroll
                for (int nt = 0; nt < 4; nt++) {
                    int n = wn * 32 + nt * 8;
                    uint32_t b0h, b0l, b1h, b1l;
                    split_tf32(Bs_[(kb + tig)     * BSS + n + gid], b0h, b0l);
                    split_tf32(Bs_[(kb + tig + 4) * BSS + n + gid], b1h, b1l);
#pragma unroll
                    for (int mt = 0; mt < 2; mt++) {
                        mma_tf32(acc[mt][nt], ah[mt][0], ah[mt][1], ah[mt][2], ah[mt][3], b0h, b1h);
                        mma_tf32(acc[mt][nt], al[mt][0], al[mt][1], al[mt][2], al[mt][3], b0h, b1h);
                        mma_tf32(acc[mt][nt], ah[mt][0], ah[mt][1], ah[mt][2], ah[mt][3], b0l, b1l);
                    }
                }
            }
        }

        __syncthreads();
        if (has_next) {
            sts_tile();
            __syncthreads();
        }
    }

    // Epilogue: stage 32 rows (fp32) then emit bf16 hi/lo.
    float* stage = As_;                 // 32 x 68
    const int bb    = m0 >> 10;
    const int tbase = m0 & 1023;
    const size_t slab_t = (size_t)0;    // per-h slab computed below
#pragma unroll 1
    for (int pass = 0; pass < 4; pass++) {
        __syncthreads();
        if (wm == pass) {
#pragma unroll
            for (int mt = 0; mt < 2; mt++) {
#pragma unroll
                for (int nt = 0; nt < 4; nt++) {
                    int rl = mt * 16 + gid;
                    int cl = wn * 32 + nt * 8 + tig * 2;
                    float4 v = acc[mt][nt];
                    *(float2*)&stage[rl * 68 + cl]       = make_float2(v.x, v.y);
                    *(float2*)&stage[(rl + 8) * 68 + cl] = make_float2(v.z, v.w);
                }
            }
        }
        __syncthreads();
        int tp = tbase + pass * 32;
        (void)slab_t;
        if (WHICH < 2) {
            // K/Q: thread = (t, h); 8 consecutive d -> uint4 of bf16, hi & lo
            int t = tid & 31;
            int h = (tid >> 5) & 7;
            float v[8];
#pragma unroll
            for (int dl = 0; dl < 8; dl++)
                v[dl] = stage[t * 68 + dl * 8 + h];
            uint32_t ph[4], pl[4];
#pragma unroll
            for (int j = 0; j < 4; j++) {
                __nv_bfloat16 h0, l0, h1, l1;
                bf_split(v[2*j],   h0, l0);
                bf_split(v[2*j+1], h1, l1);
                ph[j] = pack_bf2(h0, h1);
                pl[j] = pack_bf2(l0, l1);
            }
            size_t off = (size_t)(bb * NH + h) * TD + (size_t)(tp + t) * 64 + (n0 >> 3);
            if (WHICH == 0) {
                *(uint4*)(g_Kh + off) = *(uint4*)ph;
                *(uint4*)(g_Kl + off) = *(uint4*)pl;
            } else {
                *(uint4*)(g_Qh + off) = *(uint4*)ph;
                *(uint4*)(g_Ql + off) = *(uint4*)pl;
            }
        } else {
            // V transposed: thread = (dl, h, tq); 8 consecutive t -> uint4
            int dl = tid & 7;
            int h  = (tid >> 3) & 7;
            int tq = tid >> 6;          // 0..3
            uint32_t ph[4], pl[4];
#pragma unroll
            for (int j = 0; j < 4; j++) {
                int t0 = tq * 8 + 2 * j;
                float v0 = stage[t0 * 68 + dl * 8 + h];
                float v1 = stage[(t0 + 1) * 68 + dl * 8 + h];
                __nv_bfloat16 h0, l0, h1, l1;
                bf_split(v0, h0, l0);
                bf_split(v1, h1, l1);
                ph[j] = pack_bf2(h0, h1);
                pl[j] = pack_bf2(l0, l1);
            }
            int d = (n0 >> 3) + dl;
            size_t off = (size_t)(bb * NH + h) * TD + (size_t)d * T_ + tp + tq * 8;
            *(uint4*)(g_Vth + off) = *(uint4*)ph;
            *(uint4*)(g_Vtl + off) = *(uint4*)pl;
        }
    }
}

// ---------------------------------------------------------------------------
// Kernel 2: flash attention on bf16 m16n8k16 with 3xBF16 splitting.
// Paired q-blocks (j, 7-j): 256 uniform CTAs. S: Qh*Kh + Ql*Kh + Qh*Kl.
// PV: Ph*Vh + Pl*Vh + Ph*Vl with V transposed in smem.
// All smem frag gathers use u32-stride 36 (banks 4*gid+tig, conflict-free).
// ---------------------------------------------------------------------------
#define KSTR 72   // bf16 stride (= 36 u32)
#define ATTN_SMEM_BYTES (4*64*KSTR*2 + 2*8*16*KSTR*2 + 64*4)   // 73984

__global__ __launch_bounds__(256, 2) void attn_kernel(
    const int* __restrict__ key_seq, float* __restrict__ out)
{
    extern __shared__ char asmem[];
    __nv_bfloat16* Ksh = (__nv_bfloat16*)asmem;        // [64][KSTR]
    __nv_bfloat16* Ksl = Ksh + 64 * KSTR;
    __nv_bfloat16* Vsh = Ksl + 64 * KSTR;              // transposed [64 d][KSTR t]
    __nv_bfloat16* Vsl = Vsh + 64 * KSTR;
    __nv_bfloat16* Ph  = Vsl + 64 * KSTR;              // per-warp [16][KSTR]
    __nv_bfloat16* Pl  = Ph + 8 * 16 * KSTR;
    float* sbias = (float*)(Pl + 8 * 16 * KSTR);       // [64]

    uint32_t* K32h = (uint32_t*)Ksh;
    uint32_t* K32l = (uint32_t*)Ksl;
    uint32_t* V32h = (uint32_t*)Vsh;
    uint32_t* V32l = (uint32_t*)Vsl;

    const int tid  = threadIdx.x;
    const int lane = tid & 31;
    const int w    = tid >> 5;
    const int gid  = lane >> 2;
    const int tig  = lane & 3;
    const int bh   = blockIdx.y;
    const int b    = bh >> 3;
    const int h    = bh & 7;
    const size_t base = (size_t)bh * TD;

    const __nv_bfloat16* gQh = g_Qh + base;
    const __nv_bfloat16* gQl = g_Ql + base;
    const __nv_bfloat16* gKh = g_Kh + base;
    const __nv_bfloat16* gKl = g_Kl + base;
    const __nv_bfloat16* gVh = g_Vth + base;
    const __nv_bfloat16* gVl = g_Vtl + base;
    const int* ksq = key_seq + b * T_;

    uint32_t* P32h = (uint32_t*)(Ph + w * 16 * KSTR);
    uint32_t* P32l = (uint32_t*)(Pl + w * 16 * KSTR);

#pragma unroll 1
    for (int pi = 0; pi < 2; pi++) {
        const int blk = pi ? (7 - blockIdx.x) : blockIdx.x;
        const int q0  = blk * 128;
        const int qlo = q0 + w * 16 + gid;
        const int qhi = qlo + 8;

        // Q fragments (hi & lo) in registers
        uint32_t qh[4][4], ql[4][4];
#pragma unroll
        for (int kt = 0; kt < 4; kt++) {
            const __nv_bfloat16* rlo = gQh + (size_t)qlo * 64 + kt * 16;
            const __nv_bfloat16* rhi = gQh + (size_t)qhi * 64 + kt * 16;
            qh[kt][0] = *(const uint32_t*)(rlo + tig * 2);
            qh[kt][1] = *(const uint32_t*)(rhi + tig * 2);
            qh[kt][2] = *(const uint32_t*)(rlo + 8 + tig * 2);
            qh[kt][3] = *(const uint32_t*)(rhi + 8 + tig * 2);
            const __nv_bfloat16* slo = gQl + (size_t)qlo * 64 + kt * 16;
            const __nv_bfloat16* shi = gQl + (size_t)qhi * 64 + kt * 16;
            ql[kt][0] = *(const uint32_t*)(slo + tig * 2);
            ql[kt][1] = *(const uint32_t*)(shi + tig * 2);
            ql[kt][2] = *(const uint32_t*)(slo + 8 + tig * 2);
            ql[kt][3] = *(const uint32_t*)(shi + 8 + tig * 2);
        }

        float4 acc[8];
#pragma unroll
        for (int nt = 0; nt < 8; nt++) acc[nt] = make_float4(0.f,0.f,0.f,0.f);
        float m_lo = NEG_INF, m_hi = NEG_INF, l_lo = 0.f, l_hi = 0.f;

        const int kmax  = q0 + 128;
        const int khi_w = q0 + w * 16 + 16;

        for (int kb = 0; kb < kmax; kb += 64) {
            __syncthreads();
            // K tiles: [key][d] bf16, uint4 = 8 d
            for (int f = tid; f < 512; f += 256) {
                int key = f >> 3;
                int c   = (f & 7) * 8;
                size_t go = (size_t)(kb + key) * 64 + c;
                *(uint4*)(Ksh + key * KSTR + c) = *(const uint4*)(gKh + go);
                *(uint4*)(Ksl + key * KSTR + c) = *(const uint4*)(gKl + go);
            }
            // V tiles (transposed): [d][t], uint4 = 8 t
            for (int f = tid; f < 512; f += 256) {
                int d  = f >> 3;
                int tc = (f & 7) * 8;
                size_t go = (size_t)d * T_ + kb + tc;
                *(uint4*)(Vsh + d * KSTR + tc) = *(const uint4*)(gVh + go);
                *(uint4*)(Vsl + d * KSTR + tc) = *(const uint4*)(gVl + go);
            }
            if (tid < 64)
                sbias[tid] = (ksq[kb + tid] < 0) ? NEG_INF : 0.f;
            __syncthreads();

            if (kb >= khi_w) continue;

            // ---- S = Q . K^T  (3xBF16) ----
            float4 s[8];
#pragma unroll
            for (int nt = 0; nt < 8; nt++) s[nt] = make_float4(0.f,0.f,0.f,0.f);
#pragma unroll
            for (int kt = 0; kt < 4; kt++) {
#pragma unroll
                for (int nt = 0; nt < 8; nt++) {
                    int idx = (nt * 8 + gid) * 36 + kt * 8 + tig;
                    uint32_t b0h = K32h[idx], b1h = K32h[idx + 4];
                    uint32_t b0l = K32l[idx], b1l = K32l[idx + 4];
                    mma_bf16(s[nt], qh[kt][0], qh[kt][1], qh[kt][2], qh[kt][3], b0h, b1h);
                    mma_bf16(s[nt], ql[kt][0], ql[kt][1], ql[kt][2], ql[kt][3], b0h, b1h);
                    mma_bf16(s[nt], qh[kt][0], qh[kt][1], qh[kt][2], qh[kt][3], b0l, b1l);
                }
            }

            // ---- mask + scale ----
            float mx_lo = NEG_INF, mx_hi = NEG_INF;
#pragma unroll
            for (int nt = 0; nt < 8; nt++) {
                int ki  = kb + nt * 8 + tig * 2;
                float b0f = sbias[nt * 8 + tig * 2];
                float b1f = sbias[nt * 8 + tig * 2 + 1];
                s[nt].x = (ki     > qlo) ? NEG_INF : fmaf(s[nt].x, 0.125f, b0f);
                s[nt].y = (ki + 1 > qlo) ? NEG_INF : fmaf(s[nt].y, 0.125f, b1f);
                s[nt].z = (ki     > qhi) ? NEG_INF : fmaf(s[nt].z, 0.125f, b0f);
                s[nt].w = (ki + 1 > qhi) ? NEG_INF : fmaf(s[nt].w, 0.125f, b1f);
                mx_lo = fmaxf(mx_lo, fmaxf(s[nt].x, s[nt].y));
                mx_hi = fmaxf(mx_hi, fmaxf(s[nt].z, s[nt].w));
            }
            mx_lo = fmaxf(mx_lo, __shfl_xor_sync(0xffffffffu, mx_lo, 1));
            mx_lo = fmaxf(mx_lo, __shfl_xor_sync(0xffffffffu, mx_lo, 2));
            mx_hi = fmaxf(mx_hi, __shfl_xor_sync(0xffffffffu, mx_hi, 1));
            mx_hi = fmaxf(mx_hi, __shfl_xor_sync(0xffffffffu, mx_hi, 2));

            float mn_lo = fmaxf(m_lo, mx_lo);
            float mn_hi = fmaxf(m_hi, mx_hi);
            float al_lo = __expf(m_lo - mn_lo);
            float al_hi = __expf(m_hi - mn_hi);

            float sum_lo = 0.f, sum_hi = 0.f;
#pragma unroll
            for (int nt = 0; nt < 8; nt++) {
                s[nt].x = __expf(s[nt].x - mn_lo);
                s[nt].y = __expf(s[nt].y - mn_lo);
                s[nt].z = __expf(s[nt].z - mn_hi);
                s[nt].w = __expf(s[nt].w - mn_hi);
                sum_lo += s[nt].x + s[nt].y;
                sum_hi += s[nt].z + s[nt].w;
            }
            sum_lo += __shfl_xor_sync(0xffffffffu, sum_lo, 1);
            sum_lo += __shfl_xor_sync(0xffffffffu, sum_lo, 2);
            sum_hi += __shfl_xor_sync(0xffffffffu, sum_hi, 1);
            sum_hi += __shfl_xor_sync(0xffffffffu, sum_hi, 2);

            l_lo = l_lo * al_lo + sum_lo;  m_lo = mn_lo;
            l_hi = l_hi * al_hi + sum_hi;  m_hi = mn_hi;

#pragma unroll
            for (int nt = 0; nt < 8; nt++) {
                acc[nt].x *= al_lo;  acc[nt].y *= al_lo;
                acc[nt].z *= al_hi;  acc[nt].w *= al_hi;
            }

            // ---- P -> per-warp smem as bf16 hi/lo pairs ----
#pragma unroll
            for (int nt = 0; nt < 8; nt++) {
                __nv_bfloat16 hx, lx, hy, ly, hz, lz, hw, lw;
                bf_split(s[nt].x, hx, lx);
                bf_split(s[nt].y, hy, ly);
                bf_split(s[nt].z, hz, lz);
                bf_split(s[nt].w, hw, lw);
                int c = nt * 4 + tig;
                P32h[gid * 36 + c]       = pack_bf2(hx, hy);
                P32l[gid * 36 + c]       = pack_bf2(lx, ly);
                P32h[(gid + 8) * 36 + c] = pack_bf2(hz, hw);
                P32l[(gid + 8) * 36 + c] = pack_bf2(lz, lw);
            }
            __syncwarp();

            // ---- O += P . V  (3xBF16, V transposed) ----
#pragma unroll
            for (int kt = 0; kt < 4; kt++) {
                uint32_t pah[4], pal[4];
                pah[0] = P32h[gid * 36 + kt * 8 + tig];
                pah[1] = P32h[(gid + 8) * 36 + kt * 8 + tig];
                pah[2] = P32h[gid * 36 + kt * 8 + tig + 4];
                pah[3] = P32h[(gid + 8) * 36 + kt * 8 + tig + 4];
                pal[0] = P32l[gid * 36 + kt * 8 + tig];
                pal[1] = P32l[(gid + 8) * 36 + kt * 8 + tig];
                pal[2] = P32l[gid * 36 + kt * 8 + tig + 4];
                pal[3] = P32l[(gid + 8) * 36 + kt * 8 + tig + 4];
#pragma unroll
                for (int nt = 0; nt < 8; nt++) {
                    int idx = (nt * 8 + gid) * 36 + kt * 8 + tig;
                    uint32_t b0h = V32h[idx], b1h = V32h[idx + 4];
                    uint32_t b0l = V32l[idx], b1l = V32l[idx + 4];
                    mma_bf16(acc[nt], pah[0], pah[1], pah[2], pah[3], b0h, b1h);
                    mma_bf16(acc[nt], pal[0], pal[1], pal[2], pal[3], b0h, b1h);
                    mma_bf16(acc[nt], pah[0], pah[1], pah[2], pah[3], b0l, b1l);
                }
            }
        }

        // Epilogue for this q-block
        float il_lo = 1.f / l_lo;
        float il_hi = 1.f / l_hi;
#pragma unroll
        for (int nt = 0; nt < 8; nt++) {
            int col = h * DH + nt * 8 + tig * 2;
            *(float2*)(out + (size_t)(b * T_ + qlo) * (NH * DH) + col) =
                make_float2(acc[nt].x * il_lo, acc[nt].y * il_lo);
            *(float2*)(out + (size_t)(b * T_ + qhi) * (NH * DH) + col) =
                make_float2(acc[nt].z * il_hi, acc[nt].w * il_hi);
        }
    }
}

// ---------------------------------------------------------------------------
extern "C" void kernel_launch(void* const* d_in, const int* in_sizes, int n_in,
                              void* d_out, int out_size)
{
    const float* keys    = (const float*)d_in[0];
    const float* queries = (const float*)d_in[1];
    const float* values  = (const float*)d_in[2];
    const float* Wk      = (const float*)d_in[3];
    const float* Wq      = (const float*)d_in[4];
    const float* Wv      = (const float*)d_in[5];
    const int*   key_seq = (const int*)d_in[6];
    float* out = (float*)d_out;

    dim3 g1(512 / 64, (B_ * T_) / 128);
    proj_kernel<false, 0><<<g1, 256>>>(keys,    Wk);
    proj_kernel<false, 1><<<g1, 256>>>(queries, Wq);
    proj_kernel<true,  2><<<g1, 256>>>(values,  Wv);

    cudaFuncSetAttribute(attn_kernel,
                         cudaFuncAttributeMaxDynamicSharedMemorySize, ATTN_SMEM_BYTES);
    dim3 g2(4, BH);
    attn_kernel<<<g2, 256, ATTN_SMEM_BYTES>>>(key_seq, out);
}